// round 12
// baseline (speedup 1.0000x reference)
#include <cuda_runtime.h>
#include <cuda_fp16.h>
#include <cstdint>
#include <math.h>

#define BATCH 4
#define CIN   512
#define CK    256
#define CV    256
#define QKV   768
#define NPIX  4096
#define EPSBN 1e-5f

#define KP_X   512
#define KP_QK  256
#define KP_CTX 256

// ---------------- scratch globals --------------------------------------------
static __device__ __half g_wqkv2[(size_t)QKV * KP_X];
static __device__ __half g_wW2[(size_t)CIN * KP_CTX];
static __device__ float g_bias[QKV];
static __device__ __half g_xt2[(size_t)BATCH * NPIX * KP_X];
static __device__ __half g_Zh[(size_t)BATCH * QKV * NPIX];
static __device__ float g_stat[1024];
static __device__ float g_bnA[2 * CK], g_bnB[2 * CK];
static __device__ __half g_qt2[(size_t)BATCH * NPIX * KP_QK];
static __device__ __half g_kt2[(size_t)BATCH * NPIX * KP_QK];
static __device__ __half g_ctx2[(size_t)BATCH * NPIX * KP_CTX];

// ---------------- helpers ----------------------------------------------------
__device__ __forceinline__ uint32_t smem_u32(const void* p) {
    uint32_t a;
    asm("{ .reg .u64 t; cvta.to.shared.u64 t, %1; cvt.u32.u64 %0, t; }" : "=r"(a) : "l"(p));
    return a;
}
__device__ __forceinline__ void cp16(uint32_t dst, const void* src) {
    asm volatile("cp.async.cg.shared.global [%0], [%1], 16;" :: "r"(dst), "l"(src));
}
__device__ __forceinline__ void cp_commit() { asm volatile("cp.async.commit_group;" ::: "memory"); }
__device__ __forceinline__ void cp_wait1()  { asm volatile("cp.async.wait_group 1;" ::: "memory"); }

__device__ __forceinline__ uint32_t lds32(uint32_t a) {
    uint32_t v;
    asm volatile("ld.shared.b32 %0, [%1];" : "=r"(v) : "r"(a));
    return v;
}
__device__ __forceinline__ void ldsm4(uint32_t* r, uint32_t addr) {
    asm volatile("ldmatrix.sync.aligned.m8n8.x4.shared.b16 {%0,%1,%2,%3}, [%4];"
        : "=r"(r[0]), "=r"(r[1]), "=r"(r[2]), "=r"(r[3]) : "r"(addr));
}
__device__ __forceinline__ void mma16816(float* d, const uint32_t* a, uint32_t b0, uint32_t b1) {
    asm volatile(
        "mma.sync.aligned.m16n8k16.row.col.f32.f16.f16.f32 "
        "{%0,%1,%2,%3}, {%4,%5,%6,%7}, {%8,%9}, {%0,%1,%2,%3};"
        : "+f"(d[0]), "+f"(d[1]), "+f"(d[2]), "+f"(d[3])
        : "r"(a[0]), "r"(a[1]), "r"(a[2]), "r"(a[3]), "r"(b0), "r"(b1));
}
__device__ __forceinline__ uint32_t packh2(float lo, float hi) {
    __half2 h = __floats2half2_rn(lo, hi);
    return *(uint32_t*)&h;
}
__device__ __forceinline__ uint32_t ex2h2(uint32_t t) {
    uint32_t p;
    asm("ex2.approx.f16x2 %0, %1;" : "=r"(p) : "r"(t));
    return p;
}

// ---------------- generic fp16 NT GEMM on HMMA (R10 version) ------------------
#define ROWB 80
#define OPB  10240
#define STG  20480

__global__ void __launch_bounds__(256, 2)
gemm_fp16(const __half* __restrict__ A, const __half* __restrict__ B,
          float* __restrict__ C, __half* __restrict__ Ch,
          int K, int nit, int ldc,
          size_t sA, size_t sB, size_t sC,
          const float* __restrict__ bias, const float* __restrict__ resid, size_t sR,
          float alpha, float* __restrict__ stats)
{
    __shared__ __align__(16) char smem[2 * STG];
    uint32_t sb = smem_u32(smem);
    int tid = threadIdx.x, wid = tid >> 5, lane = tid & 31;
    int bz = blockIdx.z;
    int i0 = blockIdx.y * 128;
    int j0 = blockIdx.x * 128;

    const char* ap = (const char*)(A + sA * bz);
    const char* bp = (const char*)(B + sB * bz);

    const char* asrc[2]; uint32_t adst[2];
    const char* bsrc[2]; uint32_t bdst[2];
    #pragma unroll
    for (int jj = 0; jj < 2; jj++) {
        int idx = tid + 256 * jj, row = idx >> 2, seg = idx & 3;
        asrc[jj] = ap + ((size_t)(i0 + row) * K) * 2 + seg * 16;
        adst[jj] = sb + row * ROWB + seg * 16;
        bsrc[jj] = bp + ((size_t)(j0 + row) * K) * 2 + seg * 16;
        bdst[jj] = sb + OPB + row * ROWB + seg * 16;
    }

    int g = lane >> 2, tg = lane & 3;
    int mw = wid >> 1, nw = wid & 1;
    uint32_t arow = sb + (mw * 32 + (lane & 15)) * ROWB + (lane >> 4) * 16;
    uint32_t brow = sb + OPB + (nw * 64 + (lane >> 4) * 8 + (lane & 7)) * ROWB
                  + ((lane >> 3) & 1) * 16;

    float acc[2][8][4];
    #pragma unroll
    for (int t = 0; t < 2; t++)
        #pragma unroll
        for (int j = 0; j < 8; j++)
            #pragma unroll
            for (int c = 0; c < 4; c++) acc[t][j][c] = 0.f;

    #pragma unroll
    for (int jj = 0; jj < 2; jj++) { cp16(adst[jj], asrc[jj]); cp16(bdst[jj], bsrc[jj]); }
    cp_commit();

    for (int it = 0; it < nit; it++) {
        if (it + 1 < nit) {
            size_t ko = (size_t)(it + 1) * 64;
            uint32_t so = ((it + 1) & 1) * STG;
            #pragma unroll
            for (int jj = 0; jj < 2; jj++) {
                cp16(adst[jj] + so, asrc[jj] + ko);
                cp16(bdst[jj] + so, bsrc[jj] + ko);
            }
        }
        cp_commit();
        cp_wait1();
        __syncthreads();

        uint32_t so = (it & 1) * STG;
        #pragma unroll
        for (int k16 = 0; k16 < 2; k16++) {
            uint32_t kb = k16 * 32;
            uint32_t a0[4], a1[4];
            ldsm4(a0, arow + so + kb);
            ldsm4(a1, arow + 16 * ROWB + so + kb);
            #pragma unroll
            for (int j2 = 0; j2 < 4; j2++) {
                uint32_t bq[4];
                ldsm4(bq, brow + so + j2 * (16 * ROWB) + kb);
                mma16816(acc[0][2 * j2],     a0, bq[0], bq[1]);
                mma16816(acc[0][2 * j2 + 1], a0, bq[2], bq[3]);
                mma16816(acc[1][2 * j2],     a1, bq[0], bq[1]);
                mma16816(acc[1][2 * j2 + 1], a1, bq[2], bq[3]);
            }
        }
        __syncthreads();
    }

    float* cb = C ? C + sC * bz : nullptr;
    __half* hb = Ch ? Ch + sC * bz : nullptr;
    const float* rb = resid ? resid + sR * bz : nullptr;
    #pragma unroll
    for (int t = 0; t < 2; t++) {
        int r0 = i0 + mw * 32 + t * 16 + g;
        int r1 = r0 + 8;
        float bi0 = bias ? bias[r0] : 0.f;
        float bi1 = bias ? bias[r1] : 0.f;
        float s0 = 0.f, q0 = 0.f, s1 = 0.f, q1 = 0.f;
        #pragma unroll
        for (int j = 0; j < 8; j++) {
            int c = j0 + nw * 64 + j * 8 + tg * 2;
            float v0 = acc[t][j][0] * alpha + bi0;
            float v1 = acc[t][j][1] * alpha + bi0;
            float v2 = acc[t][j][2] * alpha + bi1;
            float v3 = acc[t][j][3] * alpha + bi1;
            if (rb) {
                float2 x0 = *(const float2*)(rb + (size_t)r0 * ldc + c);
                float2 x1 = *(const float2*)(rb + (size_t)r1 * ldc + c);
                v0 += x0.x; v1 += x0.y; v2 += x1.x; v3 += x1.y;
            }
            s0 += v0 + v1; q0 += v0 * v0 + v1 * v1;
            s1 += v2 + v3; q1 += v2 * v2 + v3 * v3;
            if (hb) {
                *(__half2*)(hb + (size_t)r0 * ldc + c) = __floats2half2_rn(v0, v1);
                *(__half2*)(hb + (size_t)r1 * ldc + c) = __floats2half2_rn(v2, v3);
            } else {
                *(float2*)(cb + (size_t)r0 * ldc + c) = make_float2(v0, v1);
                *(float2*)(cb + (size_t)r1 * ldc + c) = make_float2(v2, v3);
            }
        }
        if (stats) {
            s0 += __shfl_xor_sync(0xffffffffu, s0, 1); s0 += __shfl_xor_sync(0xffffffffu, s0, 2);
            q0 += __shfl_xor_sync(0xffffffffu, q0, 1); q0 += __shfl_xor_sync(0xffffffffu, q0, 2);
            s1 += __shfl_xor_sync(0xffffffffu, s1, 1); s1 += __shfl_xor_sync(0xffffffffu, s1, 2);
            q1 += __shfl_xor_sync(0xffffffffu, q1, 1); q1 += __shfl_xor_sync(0xffffffffu, q1, 2);
            if (tg == 0 && r0 < 512) { atomicAdd(&stats[r0], s0); atomicAdd(&stats[512 + r0], q0); }
            if (tg == 0 && r1 < 512) { atomicAdd(&stats[r1], s1); atomicAdd(&stats[512 + r1], q1); }
        }
    }
}

// ---------------- flash attention: pipelined softmax (gemm2 deferred 1 iter) --
// m-tile 32; Q ring x3, V ring x4; single sync/iter; prefetch distance 2.
#define KROW 528
#define QROW 528
#define VROW 80                       // 64B data + 16 pad; stride 20 words: conflict-free
#define QSTG (32 * QROW)              // 16896
#define VSTG (256 * VROW)             // 20480
#define SM_Q (128 * KROW)             // 67584
#define SM_V (SM_Q + 3 * QSTG)        // 118272
#define FL_SMEM (SM_V + 4 * VSTG)     // 200192
#define MTILE 32
#define NIT (NPIX / MTILE)            // 128
#define SCL 0.0901941171f             // (1/16) * log2(e)

__global__ void __launch_bounds__(256, 1)
flash_attn(const __half* __restrict__ Kt, const __half* __restrict__ Qt,
           const __half* __restrict__ Zh, __half* __restrict__ ctx2)
{
    extern __shared__ __align__(16) char smem[];
    uint32_t sb = smem_u32(smem);
    int tid = threadIdx.x, wid = tid >> 5, lane = tid & 31;
    int g = lane >> 2, tg = lane & 3;
    int b = blockIdx.y;
    int n0 = blockIdx.x * 128;

    const char* kp = (const char*)(Kt + ((size_t)b * NPIX + n0) * CK);
    const char* qp = (const char*)(Qt + (size_t)b * NPIX * CK);
    const char* vp = (const char*)(Zh + ((size_t)b * QKV + 2 * CK) * NPIX);

    // group 0: K tile (128 x 512B) + tile 0 (Q0 + V0)
    #pragma unroll
    for (int j = 0; j < 16; j++) {
        int idx = tid + 256 * j, row = idx >> 5, seg = idx & 31;
        cp16(sb + row * KROW + seg * 16, kp + (size_t)row * 512 + seg * 16);
    }
    #pragma unroll
    for (int j = 0; j < 4; j++) {
        int idx = tid + 256 * j;
        int qrow = idx >> 5, qseg = idx & 31;
        cp16(sb + SM_Q + qrow * QROW + qseg * 16, qp + (size_t)qrow * 512 + qseg * 16);
        int vrow = idx >> 2, vseg = idx & 3;
        cp16(sb + SM_V + vrow * VROW + vseg * 16, vp + ((size_t)vrow * NPIX) * 2 + vseg * 16);
    }
    cp_commit();
    // group 1: tile 1
    #pragma unroll
    for (int j = 0; j < 4; j++) {
        int idx = tid + 256 * j;
        int qrow = idx >> 5, qseg = idx & 31;
        cp16(sb + SM_Q + QSTG + qrow * QROW + qseg * 16,
             qp + (size_t)(MTILE + qrow) * 512 + qseg * 16);
        int vrow = idx >> 2, vseg = idx & 3;
        cp16(sb + SM_V + VSTG + vrow * VROW + vseg * 16,
             vp + ((size_t)vrow * NPIX + MTILE) * 2 + vseg * 16);
    }
    cp_commit();

    float o[32][4];
    #pragma unroll
    for (int j = 0; j < 32; j++)
        #pragma unroll
        for (int c = 0; c < 4; c++) o[j][c] = 0.f;
    float osum[4] = {0.f, 0.f, 0.f, 0.f};
    float m0 = -1e30f, m8 = -1e30f;
    uint32_t app[2][4];   // deferred P fragments (gemm2 operand for prev iter)

    uint32_t arow = sb + (wid * 16 + (lane & 15)) * KROW + (lane >> 4) * 16;
    uint32_t qoff = ((lane >> 4) * 8 + (lane & 7)) * QROW + ((lane >> 3) & 1) * 16;
    uint32_t voff = ((lane >> 4) * 8 + (lane & 7)) * VROW + ((lane >> 3) & 1) * 16;
    const uint32_t ONESH2 = 0x3C003C00u;

    for (int it = 0; it < NIT; it++) {
        cp_wait1();
        __syncthreads();

        // ---- gemm1: S(it) = K . Q(it)^T  [16n x 32m, K'=256] ----
        uint32_t qb = sb + SM_Q + (uint32_t)(it % 3) * QSTG + qoff;
        float s[4][4];
        #pragma unroll
        for (int j = 0; j < 4; j++)
            #pragma unroll
            for (int c = 0; c < 4; c++) s[j][c] = 0.f;
        #pragma unroll
        for (int k16 = 0; k16 < 16; k16++) {
            uint32_t a[4];
            ldsm4(a, arow + k16 * 32);
            #pragma unroll
            for (int j2 = 0; j2 < 2; j2++) {
                uint32_t bq[4];
                ldsm4(bq, qb + j2 * (16 * QROW) + k16 * 32);
                mma16816(s[2 * j2],     a, bq[0], bq[1]);
                mma16816(s[2 * j2 + 1], a, bq[2], bq[3]);
            }
        }

        // ---- gemm2(it-1): O += P_prev . V(it-1)^T  (tensor work during softmax slack) ----
        if (it) {
            uint32_t vb = sb + SM_V + (uint32_t)((it - 1) & 3) * VSTG + voff;
            #pragma unroll
            for (int t = 0; t < 2; t++) {
                mma16816(osum, app[t], ONESH2, ONESH2);
                #pragma unroll
                for (int j4 = 0; j4 < 16; j4++) {
                    uint32_t bv[4];
                    ldsm4(bv, vb + j4 * (16 * VROW) + t * 32);
                    mma16816(o[2 * j4],     app[t], bv[0], bv[1]);
                    mma16816(o[2 * j4 + 1], app[t], bv[2], bv[3]);
                }
            }
        }

        // ---- softmax(it): raw-units max; scaled exp via f16x2 ----
        float mx0 = -1e30f, mx8 = -1e30f;
        #pragma unroll
        for (int j = 0; j < 4; j++) {
            mx0 = fmaxf(mx0, fmaxf(s[j][0], s[j][1]));
            mx8 = fmaxf(mx8, fmaxf(s[j][2], s[j][3]));
        }
        mx0 = fmaxf(mx0, __shfl_xor_sync(0xffffffffu, mx0, 1));
        mx0 = fmaxf(mx0, __shfl_xor_sync(0xffffffffu, mx0, 2));
        mx8 = fmaxf(mx8, __shfl_xor_sync(0xffffffffu, mx8, 1));
        mx8 = fmaxf(mx8, __shfl_xor_sync(0xffffffffu, mx8, 2));
        float nm0 = fmaxf(m0, mx0), nm8 = fmaxf(m8, mx8);
        float sc0 = __expf((m0 - nm0) * 0.0625f);
        float sc8 = __expf((m8 - nm8) * 0.0625f);
        m0 = nm0; m8 = nm8;
        float c0 = m0 * SCL, c8 = m8 * SCL;

        #pragma unroll
        for (int j = 0; j < 4; j++) {
            float t0 = fmaf(s[j][0], SCL, -c0);
            float t1 = fmaf(s[j][1], SCL, -c0);
            float t2 = fmaf(s[j][2], SCL, -c8);
            float t3 = fmaf(s[j][3], SCL, -c8);
            uint32_t ph0 = ex2h2(packh2(t0, t1));   // row g
            uint32_t ph1 = ex2h2(packh2(t2, t3));   // row g+8
            app[j >> 1][(j & 1) * 2]     = ph0;
            app[j >> 1][(j & 1) * 2 + 1] = ph1;
        }

        if (sc0 != 1.f || sc8 != 1.f) {
            #pragma unroll
            for (int j = 0; j < 32; j++) {
                o[j][0] *= sc0; o[j][1] *= sc0;
                o[j][2] *= sc8; o[j][3] *= sc8;
            }
            osum[0] *= sc0; osum[1] *= sc0;
            osum[2] *= sc8; osum[3] *= sc8;
        }

        // ---- prefetch tile it+2 ----
        if (it + 2 < NIT) {
            int tn = it + 2;
            uint32_t qdst = sb + SM_Q + (uint32_t)(tn % 3) * QSTG;
            uint32_t vdst = sb + SM_V + (uint32_t)(tn & 3) * VSTG;
            size_t mo = (size_t)tn * MTILE;
            #pragma unroll
            for (int j = 0; j < 4; j++) {
                int idx = tid + 256 * j;
                int qrow = idx >> 5, qseg = idx & 31;
                cp16(qdst + qrow * QROW + qseg * 16,
                     qp + (mo + qrow) * 512 + qseg * 16);
                int vrow = idx >> 2, vseg = idx & 3;
                cp16(vdst + vrow * VROW + vseg * 16,
                     vp + ((size_t)vrow * NPIX + mo) * 2 + vseg * 16);
            }
        }
        cp_commit();
    }

    // ---- final gemm2 for last tile ----
    {
        uint32_t vb = sb + SM_V + (uint32_t)((NIT - 1) & 3) * VSTG + voff;
        #pragma unroll
        for (int t = 0; t < 2; t++) {
            mma16816(osum, app[t], ONESH2, ONESH2);
            #pragma unroll
            for (int j4 = 0; j4 < 16; j4++) {
                uint32_t bv[4];
                ldsm4(bv, vb + j4 * (16 * VROW) + t * 32);
                mma16816(o[2 * j4],     app[t], bv[0], bv[1]);
                mma16816(o[2 * j4 + 1], app[t], bv[2], bv[3]);
            }
        }
    }

    float i0 = 1.f / osum[0], i8 = 1.f / osum[2];
    int nrow = n0 + wid * 16 + g;
    __half2* out0 = (__half2*)(ctx2 + ((size_t)b * NPIX + nrow) * CV);
    __half2* out8 = (__half2*)(ctx2 + ((size_t)b * NPIX + nrow + 8) * CV);
    #pragma unroll
    for (int j2 = 0; j2 < 32; j2++) {
        int cp_ = 4 * j2 + tg;
        out0[cp_] = __floats2half2_rn(o[j2][0] * i0, o[j2][1] * i0);
        out8[cp_] = __floats2half2_rn(o[j2][2] * i8, o[j2][3] * i8);
    }
}

// ---------------- prep / converts ---------------------------------------------
__global__ void __launch_bounds__(256) zero_stats()
{
    g_stat[blockIdx.x * 256 + threadIdx.x] = 0.f;
}

__global__ void __launch_bounds__(256) prep_w(
    const float* __restrict__ wq, const float* __restrict__ bq,
    const float* __restrict__ wk, const float* __restrict__ bk,
    const float* __restrict__ wv, const float* __restrict__ bv,
    const float* __restrict__ wW)
{
    int idx = blockIdx.x * 256 + threadIdx.x;
    {
        int o = idx / CIN, c = idx % CIN;
        float v = (o < CK) ? wq[o * CIN + c] : (o < 2 * CK) ? wk[(o - CK) * CIN + c]
                                                            : wv[(o - 2 * CK) * CIN + c];
        g_wqkv2[(size_t)o * KP_X + c] = __float2half(v);
    }
    if (idx < CIN * CV) {
        int co = idx / CV, cv = idx % CV;
        g_wW2[(size_t)co * KP_CTX + cv] = __float2half(wW[co * CV + cv]);
    }
    if (idx < QKV)
        g_bias[idx] = (idx < CK) ? bq[idx] : (idx < 2 * CK) ? bk[idx - CK] : bv[idx - 2 * CK];
}

__global__ void __launch_bounds__(256) transpose_x(const float* __restrict__ x)
{
    __shared__ float tile[32][33];
    int b = blockIdx.z, c0 = blockIdx.y * 32, n0 = blockIdx.x * 32;
    int tx = threadIdx.x & 31, ty = threadIdx.x >> 5;
    const float* xp = x + ((size_t)b * CIN + c0) * NPIX + n0;
    #pragma unroll
    for (int r = ty; r < 32; r += 8) tile[r][tx] = xp[(size_t)r * NPIX + tx];
    __syncthreads();
    __half* op = g_xt2 + ((size_t)b * NPIX + n0) * KP_X + c0;
    #pragma unroll
    for (int r = ty; r < 32; r += 8)
        op[(size_t)r * KP_X + tx] = __float2half(tile[tx][r]);
}

__global__ void __launch_bounds__(256) bn_finalize(
    const float* __restrict__ gq, const float* __restrict__ betaq,
    const float* __restrict__ gk, const float* __restrict__ betak)
{
    int o = blockIdx.x * 256 + threadIdx.x;
    float cnt = (float)(BATCH * NPIX);
    float mean = g_stat[o] / cnt;
    float var = g_stat[512 + o] / cnt - mean * mean;
    float inv = rsqrtf(var + EPSBN);
    float gamma = (o < CK) ? gq[o] : gk[o - CK];
    float beta  = (o < CK) ? betaq[o] : betak[o - CK];
    g_bnA[o] = gamma * inv;
    g_bnB[o] = beta - mean * gamma * inv;
}

__global__ void __launch_bounds__(256) convert_qk()
{
    __shared__ float tile[32][33];
    int b = blockIdx.z, o0 = blockIdx.y * 32, n0 = blockIdx.x * 32;
    int tx = threadIdx.x & 31, ty = threadIdx.x >> 5;
    #pragma unroll
    for (int r = ty; r < 32; r += 8) {
        int o = o0 + r;
        float z = __half2float(g_Zh[((size_t)b * QKV + o) * NPIX + n0 + tx]) * g_bnA[o] + g_bnB[o];
        tile[r][tx] = z > 0.f ? z : 0.f;
    }
    __syncthreads();
    bool isq = (o0 < CK);
    __half* base = isq ? g_qt2 : g_kt2;
    int oc = o0 & (CK - 1);
    __half* op = base + ((size_t)b * NPIX + n0) * KP_QK + oc;
    #pragma unroll
    for (int r = ty; r < 32; r += 8)
        op[(size_t)r * KP_QK + tx] = __float2half(tile[tx][r]);
}

// ---------------- launch ------------------------------------------------------
extern "C" void kernel_launch(void* const* d_in, const int* in_sizes, int n_in,
                              void* d_out, int out_size)
{
    const float* x     = (const float*)d_in[0];
    const float* wq    = (const float*)d_in[1];
    const float* bq    = (const float*)d_in[2];
    const float* gq    = (const float*)d_in[3];
    const float* betaq = (const float*)d_in[4];
    const float* wk    = (const float*)d_in[5];
    const float* bk    = (const float*)d_in[6];
    const float* gk    = (const float*)d_in[7];
    const float* betak = (const float*)d_in[8];
    const float* wv    = (const float*)d_in[9];
    const float* bv    = (const float*)d_in[10];
    const float* wW    = (const float*)d_in[11];
    const float* bW    = (const float*)d_in[12];
    float* out = (float*)d_out;

    cudaFuncSetAttribute(flash_attn, cudaFuncAttributeMaxDynamicSharedMemorySize, FL_SMEM);

    void *pwqkv2, *pwW2, *pbias, *pxt2, *pZh, *pqt2, *pkt2, *pctx2, *pstat;
    cudaGetSymbolAddress(&pwqkv2, g_wqkv2);
    cudaGetSymbolAddress(&pwW2, g_wW2);
    cudaGetSymbolAddress(&pbias, g_bias);
    cudaGetSymbolAddress(&pxt2, g_xt2);
    cudaGetSymbolAddress(&pZh, g_Zh);
    cudaGetSymbolAddress(&pqt2, g_qt2);
    cudaGetSymbolAddress(&pkt2, g_kt2);
    cudaGetSymbolAddress(&pctx2, g_ctx2);
    cudaGetSymbolAddress(&pstat, g_stat);

    // 1. prep weights/bias; transpose x; zero stats
    prep_w<<<(QKV * CIN) / 256, 256>>>(wq, bq, wk, bk, wv, bv, wW);
    transpose_x<<<dim3(NPIX / 32, CIN / 32, BATCH), 256>>>(x);
    zero_stats<<<4, 256>>>();

    // 2. qkv projection -> fp16 Zh + fused BN stats
    gemm_fp16<<<dim3(NPIX / 128, QKV / 128, BATCH), 256>>>(
        (const __half*)pwqkv2, (const __half*)pxt2, nullptr, (__half*)pZh,
        KP_X, KP_X / 32, NPIX,
        0, (size_t)NPIX * KP_X, (size_t)QKV * NPIX,
        (const float*)pbias, nullptr, 0, 1.0f, (float*)pstat);

    // 3. finalize BN; BN+ReLU+transpose q/k
    bn_finalize<<<2, 256>>>(gq, betaq, gk, betak);
    convert_qk<<<dim3(NPIX / 32, (2 * CK) / 32, BATCH), 256>>>();

    // 4-6. fused attention (pipelined softmax)
    flash_attn<<<dim3(NPIX / 128, BATCH), 256, FL_SMEM>>>(
        (const __half*)pkt2, (const __half*)pqt2, (const __half*)pZh, (__half*)pctx2);

    // 7. out conv + residual
    gemm_fp16<<<dim3(NPIX / 128, CIN / 128, BATCH), 256>>>(
        (const __half*)pwW2, (const __half*)pctx2, out, nullptr,
        KP_CTX, KP_CTX / 32, NPIX,
        0, (size_t)NPIX * KP_CTX, (size_t)CIN * NPIX,
        bW, x, (size_t)CIN * NPIX, 1.0f, nullptr);
}

// round 13
// speedup vs baseline: 1.0191x; 1.0191x over previous
#include <cuda_runtime.h>
#include <cuda_fp16.h>
#include <cstdint>
#include <math.h>

#define BATCH 4
#define CIN   512
#define CK    256
#define CV    256
#define QKV   768
#define NPIX  4096
#define EPSBN 1e-5f

#define KP_X   512
#define KP_QK  256
#define KP_CTX 256

// ---------------- scratch globals --------------------------------------------
static __device__ __half g_wqkv2[(size_t)QKV * KP_X];
static __device__ __half g_wW2[(size_t)CIN * KP_CTX];
static __device__ float g_bias[QKV];
static __device__ __half g_xt2[(size_t)BATCH * NPIX * KP_X];
static __device__ __half g_Zh[(size_t)BATCH * QKV * NPIX];
static __device__ float g_stat[1024];
static __device__ float g_bnA[2 * CK], g_bnB[2 * CK];
static __device__ __half g_qt2[(size_t)BATCH * NPIX * KP_QK];
static __device__ __half g_kt2[(size_t)BATCH * NPIX * KP_QK];
static __device__ __half g_ctx2[(size_t)BATCH * NPIX * KP_CTX];

// ---------------- helpers ----------------------------------------------------
__device__ __forceinline__ uint32_t smem_u32(const void* p) {
    uint32_t a;
    asm("{ .reg .u64 t; cvta.to.shared.u64 t, %1; cvt.u32.u64 %0, t; }" : "=r"(a) : "l"(p));
    return a;
}
__device__ __forceinline__ void cp16(uint32_t dst, const void* src) {
    asm volatile("cp.async.cg.shared.global [%0], [%1], 16;" :: "r"(dst), "l"(src));
}
__device__ __forceinline__ void cp_commit() { asm volatile("cp.async.commit_group;" ::: "memory"); }
__device__ __forceinline__ void cp_wait1()  { asm volatile("cp.async.wait_group 1;" ::: "memory"); }

__device__ __forceinline__ void ldsm4(uint32_t* r, uint32_t addr) {
    asm volatile("ldmatrix.sync.aligned.m8n8.x4.shared.b16 {%0,%1,%2,%3}, [%4];"
        : "=r"(r[0]), "=r"(r[1]), "=r"(r[2]), "=r"(r[3]) : "r"(addr));
}
__device__ __forceinline__ void mma16816(float* d, const uint32_t* a, uint32_t b0, uint32_t b1) {
    asm volatile(
        "mma.sync.aligned.m16n8k16.row.col.f32.f16.f16.f32 "
        "{%0,%1,%2,%3}, {%4,%5,%6,%7}, {%8,%9}, {%0,%1,%2,%3};"
        : "+f"(d[0]), "+f"(d[1]), "+f"(d[2]), "+f"(d[3])
        : "r"(a[0]), "r"(a[1]), "r"(a[2]), "r"(a[3]), "r"(b0), "r"(b1));
}
__device__ __forceinline__ uint32_t packh2(float lo, float hi) {
    __half2 h = __floats2half2_rn(lo, hi);
    return *(uint32_t*)&h;
}
__device__ __forceinline__ uint32_t ex2h2(uint32_t t) {
    uint32_t p;
    asm("ex2.approx.f16x2 %0, %1;" : "=r"(p) : "r"(t));
    return p;
}

// ---------------- fp16 NT GEMM, 512 threads, tile 128x256 ---------------------
// C[i,j] = alpha * sum_k A[i,k]*B[j,k] (+bias[i]) (+resid); fp32 or fp16 out.
// 16 warps (4x4), warp tile 32x64, BK=32, 2-stage cp.async.
#define ROWB 80
#define APB  10240            // A tile bytes per stage (128*80)
#define STGB 30720            // stage bytes (A + B: 384*80)
#define GEMM_SMEM (2 * STGB)  // 61440

__global__ void __launch_bounds__(512, 1)
gemm_fp16(const __half* __restrict__ A, const __half* __restrict__ B,
          float* __restrict__ C, __half* __restrict__ Ch,
          int K, int nit, int ldc,
          size_t sA, size_t sB, size_t sC,
          const float* __restrict__ bias, const float* __restrict__ resid, size_t sR,
          float alpha, float* __restrict__ stats)
{
    extern __shared__ __align__(16) char smem[];
    uint32_t sb = smem_u32(smem);
    int tid = threadIdx.x, wid = tid >> 5, lane = tid & 31;
    int bz = blockIdx.z;
    int i0 = blockIdx.y * 128;
    int j0 = blockIdx.x * 256;

    const char* ap = (const char*)(A + sA * bz);
    const char* bp = (const char*)(B + sB * bz);

    // 1536 cp16 slots (384 rows x 4 segs) over 512 threads = 3 each
    const char* src[3]; uint32_t dst[3];
    #pragma unroll
    for (int jj = 0; jj < 3; jj++) {
        int idx = tid + 512 * jj, row = idx >> 2, seg = idx & 3;
        if (row < 128) {
            src[jj] = ap + ((size_t)(i0 + row) * K) * 2 + seg * 16;
            dst[jj] = sb + row * ROWB + seg * 16;
        } else {
            int br = row - 128;
            src[jj] = bp + ((size_t)(j0 + br) * K) * 2 + seg * 16;
            dst[jj] = sb + APB + br * ROWB + seg * 16;
        }
    }

    int g = lane >> 2, tg = lane & 3;
    int mw = wid >> 2, nw = wid & 3;
    uint32_t arow = sb + (mw * 32 + (lane & 15)) * ROWB + (lane >> 4) * 16;
    uint32_t brow = sb + APB + (nw * 64 + (lane >> 4) * 8 + (lane & 7)) * ROWB
                  + ((lane >> 3) & 1) * 16;

    float acc[2][8][4];
    #pragma unroll
    for (int t = 0; t < 2; t++)
        #pragma unroll
        for (int j = 0; j < 8; j++)
            #pragma unroll
            for (int c = 0; c < 4; c++) acc[t][j][c] = 0.f;

    #pragma unroll
    for (int jj = 0; jj < 3; jj++) cp16(dst[jj], src[jj]);
    cp_commit();

    for (int it = 0; it < nit; it++) {
        if (it + 1 < nit) {
            size_t ko = (size_t)(it + 1) * 64;
            uint32_t so = ((it + 1) & 1) * STGB;
            #pragma unroll
            for (int jj = 0; jj < 3; jj++) cp16(dst[jj] + so, src[jj] + ko);
        }
        cp_commit();
        cp_wait1();
        __syncthreads();

        uint32_t so = (it & 1) * STGB;
        #pragma unroll
        for (int k16 = 0; k16 < 2; k16++) {
            uint32_t kb = k16 * 32;
            uint32_t a0[4], a1[4];
            ldsm4(a0, arow + so + kb);
            ldsm4(a1, arow + 16 * ROWB + so + kb);
            #pragma unroll
            for (int j2 = 0; j2 < 4; j2++) {
                uint32_t bq[4];
                ldsm4(bq, brow + so + j2 * (16 * ROWB) + kb);
                mma16816(acc[0][2 * j2],     a0, bq[0], bq[1]);
                mma16816(acc[0][2 * j2 + 1], a0, bq[2], bq[3]);
                mma16816(acc[1][2 * j2],     a1, bq[0], bq[1]);
                mma16816(acc[1][2 * j2 + 1], a1, bq[2], bq[3]);
            }
        }
        __syncthreads();
    }

    float* cb = C ? C + sC * bz : nullptr;
    __half* hb = Ch ? Ch + sC * bz : nullptr;
    const float* rb = resid ? resid + sR * bz : nullptr;
    #pragma unroll
    for (int t = 0; t < 2; t++) {
        int r0 = i0 + mw * 32 + t * 16 + g;
        int r1 = r0 + 8;
        float bi0 = bias ? bias[r0] : 0.f;
        float bi1 = bias ? bias[r1] : 0.f;
        float s0 = 0.f, q0 = 0.f, s1 = 0.f, q1 = 0.f;
        #pragma unroll
        for (int j = 0; j < 8; j++) {
            int c = j0 + nw * 64 + j * 8 + tg * 2;
            float v0 = acc[t][j][0] * alpha + bi0;
            float v1 = acc[t][j][1] * alpha + bi0;
            float v2 = acc[t][j][2] * alpha + bi1;
            float v3 = acc[t][j][3] * alpha + bi1;
            if (rb) {
                float2 x0 = *(const float2*)(rb + (size_t)r0 * ldc + c);
                float2 x1 = *(const float2*)(rb + (size_t)r1 * ldc + c);
                v0 += x0.x; v1 += x0.y; v2 += x1.x; v3 += x1.y;
            }
            s0 += v0 + v1; q0 += v0 * v0 + v1 * v1;
            s1 += v2 + v3; q1 += v2 * v2 + v3 * v3;
            if (hb) {
                *(__half2*)(hb + (size_t)r0 * ldc + c) = __floats2half2_rn(v0, v1);
                *(__half2*)(hb + (size_t)r1 * ldc + c) = __floats2half2_rn(v2, v3);
            } else {
                *(float2*)(cb + (size_t)r0 * ldc + c) = make_float2(v0, v1);
                *(float2*)(cb + (size_t)r1 * ldc + c) = make_float2(v2, v3);
            }
        }
        if (stats) {
            s0 += __shfl_xor_sync(0xffffffffu, s0, 1); s0 += __shfl_xor_sync(0xffffffffu, s0, 2);
            q0 += __shfl_xor_sync(0xffffffffu, q0, 1); q0 += __shfl_xor_sync(0xffffffffu, q0, 2);
            s1 += __shfl_xor_sync(0xffffffffu, s1, 1); s1 += __shfl_xor_sync(0xffffffffu, s1, 2);
            q1 += __shfl_xor_sync(0xffffffffu, q1, 1); q1 += __shfl_xor_sync(0xffffffffu, q1, 2);
            if (tg == 0 && r0 < 512) { atomicAdd(&stats[r0], s0); atomicAdd(&stats[512 + r0], q0); }
            if (tg == 0 && r1 < 512) { atomicAdd(&stats[r1], s1); atomicAdd(&stats[512 + r1], q1); }
        }
    }
}

// ---------------- flash attention (R10 version: MTILE=64, ones-mma, f16x2 exp)
#define KROW 528
#define VROW 144
#define SM_Q 67584
#define QSTG 33792
#define SM_V (67584 + 2*33792)
#define VSTG 36864
#define FL_SMEM (135168 + 2*36864)
#define LOG2E 1.44269504f

__global__ void __launch_bounds__(256, 1)
flash_attn(const __half* __restrict__ Kt, const __half* __restrict__ Qt,
           const __half* __restrict__ Zh, __half* __restrict__ ctx2)
{
    extern __shared__ __align__(16) char smem[];
    uint32_t sb = smem_u32(smem);
    int tid = threadIdx.x, wid = tid >> 5, lane = tid & 31;
    int g = lane >> 2, tg = lane & 3;
    int b = blockIdx.y;
    int n0 = blockIdx.x * 128;

    const char* kp = (const char*)(Kt + ((size_t)b * NPIX + n0) * CK);
    const char* qp = (const char*)(Qt + (size_t)b * NPIX * CK);
    const char* vp = (const char*)(Zh + ((size_t)b * QKV + 2 * CK) * NPIX);

    #pragma unroll
    for (int j = 0; j < 16; j++) {
        int idx = tid + 256 * j, row = idx >> 5, seg = idx & 31;
        cp16(sb + row * KROW + seg * 16, kp + (size_t)row * 512 + seg * 16);
    }
    #pragma unroll
    for (int j = 0; j < 8; j++) {
        int idx = tid + 256 * j;
        int qrow = idx >> 5, qseg = idx & 31;
        cp16(sb + SM_Q + qrow * KROW + qseg * 16, qp + (size_t)qrow * 512 + qseg * 16);
        int vrow = idx >> 3, vseg = idx & 7;
        cp16(sb + SM_V + vrow * VROW + vseg * 16, vp + ((size_t)vrow * NPIX) * 2 + vseg * 16);
    }
    cp_commit();

    float o[32][4];
    #pragma unroll
    for (int j = 0; j < 32; j++)
        #pragma unroll
        for (int c = 0; c < 4; c++) o[j][c] = 0.f;
    float osum[4] = {0.f, 0.f, 0.f, 0.f};
    float m0 = -1e30f, m8 = -1e30f;

    uint32_t arow = sb + (wid * 16 + (lane & 15)) * KROW + (lane >> 4) * 16;
    uint32_t qoff = ((lane >> 4) * 8 + (lane & 7)) * KROW + ((lane >> 3) & 1) * 16;
    uint32_t voff = ((lane >> 4) * 8 + (lane & 7)) * VROW + ((lane >> 3) & 1) * 16;
    const uint32_t ONESH2 = 0x3C003C00u;

    for (int it = 0; it < NPIX / 64; it++) {
        if (it + 1 < NPIX / 64) {
            int st = (it + 1) & 1;
            size_t mo = (size_t)(it + 1) * 64;
            #pragma unroll
            for (int j = 0; j < 8; j++) {
                int idx = tid + 256 * j;
                int qrow = idx >> 5, qseg = idx & 31;
                cp16(sb + SM_Q + st * QSTG + qrow * KROW + qseg * 16,
                     qp + ((size_t)(mo + qrow)) * 512 + qseg * 16);
                int vrow = idx >> 3, vseg = idx & 7;
                cp16(sb + SM_V + st * VSTG + vrow * VROW + vseg * 16,
                     vp + ((size_t)vrow * NPIX + mo) * 2 + vseg * 16);
            }
        }
        cp_commit();
        cp_wait1();
        __syncthreads();

        int st = it & 1;
        uint32_t qb = sb + SM_Q + st * QSTG + qoff;
        uint32_t vb = sb + SM_V + st * VSTG + voff;

        float s[8][4];
        #pragma unroll
        for (int j = 0; j < 8; j++)
            #pragma unroll
            for (int c = 0; c < 4; c++) s[j][c] = 0.f;
        #pragma unroll
        for (int k16 = 0; k16 < 16; k16++) {
            uint32_t a[4];
            ldsm4(a, arow + k16 * 32);
            #pragma unroll
            for (int j2 = 0; j2 < 4; j2++) {
                uint32_t bq[4];
                ldsm4(bq, qb + j2 * (16 * KROW) + k16 * 32);
                mma16816(s[2 * j2],     a, bq[0], bq[1]);
                mma16816(s[2 * j2 + 1], a, bq[2], bq[3]);
            }
        }
        #pragma unroll
        for (int j = 0; j < 8; j++)
            #pragma unroll
            for (int c = 0; c < 4; c++) s[j][c] *= 0.0625f;

        float mx0 = -1e30f, mx8 = -1e30f;
        #pragma unroll
        for (int j = 0; j < 8; j++) {
            mx0 = fmaxf(mx0, fmaxf(s[j][0], s[j][1]));
            mx8 = fmaxf(mx8, fmaxf(s[j][2], s[j][3]));
        }
        mx0 = fmaxf(mx0, __shfl_xor_sync(0xffffffffu, mx0, 1));
        mx0 = fmaxf(mx0, __shfl_xor_sync(0xffffffffu, mx0, 2));
        mx8 = fmaxf(mx8, __shfl_xor_sync(0xffffffffu, mx8, 1));
        mx8 = fmaxf(mx8, __shfl_xor_sync(0xffffffffu, mx8, 2));
        float nm0 = fmaxf(m0, mx0), nm8 = fmaxf(m8, mx8);
        float sc0 = __expf(m0 - nm0), sc8 = __expf(m8 - nm8);
        m0 = nm0; m8 = nm8;
        float c0 = m0 * LOG2E, c8 = m8 * LOG2E;

        uint32_t pa[8][2];
        #pragma unroll
        for (int j = 0; j < 8; j++) {
            float t0 = fmaf(s[j][0], LOG2E, -c0);
            float t1 = fmaf(s[j][1], LOG2E, -c0);
            float t2 = fmaf(s[j][2], LOG2E, -c8);
            float t3 = fmaf(s[j][3], LOG2E, -c8);
            pa[j][0] = ex2h2(packh2(t0, t1));
            pa[j][1] = ex2h2(packh2(t2, t3));
        }

        if (sc0 != 1.f || sc8 != 1.f) {
            #pragma unroll
            for (int j = 0; j < 32; j++) {
                o[j][0] *= sc0; o[j][1] *= sc0;
                o[j][2] *= sc8; o[j][3] *= sc8;
            }
            osum[0] *= sc0; osum[1] *= sc0;
            osum[2] *= sc8; osum[3] *= sc8;
        }

        #pragma unroll
        for (int t = 0; t < 4; t++) {
            uint32_t a2[4] = { pa[2 * t][0], pa[2 * t][1], pa[2 * t + 1][0], pa[2 * t + 1][1] };
            mma16816(osum, a2, ONESH2, ONESH2);
            #pragma unroll
            for (int j4 = 0; j4 < 16; j4++) {
                uint32_t bv[4];
                ldsm4(bv, vb + j4 * (16 * VROW) + t * 32);
                mma16816(o[2 * j4],     a2, bv[0], bv[1]);
                mma16816(o[2 * j4 + 1], a2, bv[2], bv[3]);
            }
        }
        __syncthreads();
    }

    float i0 = 1.f / osum[0], i8 = 1.f / osum[2];
    int nrow = n0 + wid * 16 + g;
    __half2* out0 = (__half2*)(ctx2 + ((size_t)b * NPIX + nrow) * CV);
    __half2* out8 = (__half2*)(ctx2 + ((size_t)b * NPIX + nrow + 8) * CV);
    #pragma unroll
    for (int j2 = 0; j2 < 32; j2++) {
        int cp_ = 4 * j2 + tg;
        out0[cp_] = __floats2half2_rn(o[j2][0] * i0, o[j2][1] * i0);
        out8[cp_] = __floats2half2_rn(o[j2][2] * i8, o[j2][3] * i8);
    }
}

// ---------------- prep / converts ---------------------------------------------
__global__ void __launch_bounds__(256) zero_stats()
{
    g_stat[blockIdx.x * 256 + threadIdx.x] = 0.f;
}

__global__ void __launch_bounds__(256) prep_w(
    const float* __restrict__ wq, const float* __restrict__ bq,
    const float* __restrict__ wk, const float* __restrict__ bk,
    const float* __restrict__ wv, const float* __restrict__ bv,
    const float* __restrict__ wW)
{
    int idx = blockIdx.x * 256 + threadIdx.x;
    {
        int o = idx / CIN, c = idx % CIN;
        float v = (o < CK) ? wq[o * CIN + c] : (o < 2 * CK) ? wk[(o - CK) * CIN + c]
                                                            : wv[(o - 2 * CK) * CIN + c];
        g_wqkv2[(size_t)o * KP_X + c] = __float2half(v);
    }
    if (idx < CIN * CV) {
        int co = idx / CV, cv = idx % CV;
        g_wW2[(size_t)co * KP_CTX + cv] = __float2half(wW[co * CV + cv]);
    }
    if (idx < QKV)
        g_bias[idx] = (idx < CK) ? bq[idx] : (idx < 2 * CK) ? bk[idx - CK] : bv[idx - 2 * CK];
}

__global__ void __launch_bounds__(256) transpose_x(const float* __restrict__ x)
{
    __shared__ float tile[32][33];
    int b = blockIdx.z, c0 = blockIdx.y * 32, n0 = blockIdx.x * 32;
    int tx = threadIdx.x & 31, ty = threadIdx.x >> 5;
    const float* xp = x + ((size_t)b * CIN + c0) * NPIX + n0;
    #pragma unroll
    for (int r = ty; r < 32; r += 8) tile[r][tx] = xp[(size_t)r * NPIX + tx];
    __syncthreads();
    __half* op = g_xt2 + ((size_t)b * NPIX + n0) * KP_X + c0;
    #pragma unroll
    for (int r = ty; r < 32; r += 8)
        op[(size_t)r * KP_X + tx] = __float2half(tile[tx][r]);
}

__global__ void __launch_bounds__(256) bn_finalize(
    const float* __restrict__ gq, const float* __restrict__ betaq,
    const float* __restrict__ gk, const float* __restrict__ betak)
{
    int o = blockIdx.x * 256 + threadIdx.x;
    float cnt = (float)(BATCH * NPIX);
    float mean = g_stat[o] / cnt;
    float var = g_stat[512 + o] / cnt - mean * mean;
    float inv = rsqrtf(var + EPSBN);
    float gamma = (o < CK) ? gq[o] : gk[o - CK];
    float beta  = (o < CK) ? betaq[o] : betak[o - CK];
    g_bnA[o] = gamma * inv;
    g_bnB[o] = beta - mean * gamma * inv;
}

__global__ void __launch_bounds__(256) convert_qk()
{
    __shared__ float tile[32][33];
    int b = blockIdx.z, o0 = blockIdx.y * 32, n0 = blockIdx.x * 32;
    int tx = threadIdx.x & 31, ty = threadIdx.x >> 5;
    #pragma unroll
    for (int r = ty; r < 32; r += 8) {
        int o = o0 + r;
        float z = __half2float(g_Zh[((size_t)b * QKV + o) * NPIX + n0 + tx]) * g_bnA[o] + g_bnB[o];
        tile[r][tx] = z > 0.f ? z : 0.f;
    }
    __syncthreads();
    bool isq = (o0 < CK);
    __half* base = isq ? g_qt2 : g_kt2;
    int oc = o0 & (CK - 1);
    __half* op = base + ((size_t)b * NPIX + n0) * KP_QK + oc;
    #pragma unroll
    for (int r = ty; r < 32; r += 8)
        op[(size_t)r * KP_QK + tx] = __float2half(tile[tx][r]);
}

// ---------------- launch ------------------------------------------------------
extern "C" void kernel_launch(void* const* d_in, const int* in_sizes, int n_in,
                              void* d_out, int out_size)
{
    const float* x     = (const float*)d_in[0];
    const float* wq    = (const float*)d_in[1];
    const float* bq    = (const float*)d_in[2];
    const float* gq    = (const float*)d_in[3];
    const float* betaq = (const float*)d_in[4];
    const float* wk    = (const float*)d_in[5];
    const float* bk    = (const float*)d_in[6];
    const float* gk    = (const float*)d_in[7];
    const float* betak = (const float*)d_in[8];
    const float* wv    = (const float*)d_in[9];
    const float* bv    = (const float*)d_in[10];
    const float* wW    = (const float*)d_in[11];
    const float* bW    = (const float*)d_in[12];
    float* out = (float*)d_out;

    cudaFuncSetAttribute(flash_attn, cudaFuncAttributeMaxDynamicSharedMemorySize, FL_SMEM);
    cudaFuncSetAttribute(gemm_fp16, cudaFuncAttributeMaxDynamicSharedMemorySize, GEMM_SMEM);

    void *pwqkv2, *pwW2, *pbias, *pxt2, *pZh, *pqt2, *pkt2, *pctx2, *pstat;
    cudaGetSymbolAddress(&pwqkv2, g_wqkv2);
    cudaGetSymbolAddress(&pwW2, g_wW2);
    cudaGetSymbolAddress(&pbias, g_bias);
    cudaGetSymbolAddress(&pxt2, g_xt2);
    cudaGetSymbolAddress(&pZh, g_Zh);
    cudaGetSymbolAddress(&pqt2, g_qt2);
    cudaGetSymbolAddress(&pkt2, g_kt2);
    cudaGetSymbolAddress(&pctx2, g_ctx2);
    cudaGetSymbolAddress(&pstat, g_stat);

    // 1. prep weights/bias; transpose x; zero stats
    prep_w<<<(QKV * CIN) / 256, 256>>>(wq, bq, wk, bk, wv, bv, wW);
    transpose_x<<<dim3(NPIX / 32, CIN / 32, BATCH), 256>>>(x);
    zero_stats<<<4, 256>>>();

    // 2. qkv projection -> fp16 Zh + fused BN stats (tile 128x256, 512 thr)
    gemm_fp16<<<dim3(NPIX / 256, QKV / 128, BATCH), 512, GEMM_SMEM>>>(
        (const __half*)pwqkv2, (const __half*)pxt2, nullptr, (__half*)pZh,
        KP_X, KP_X / 32, NPIX,
        0, (size_t)NPIX * KP_X, (size_t)QKV * NPIX,
        (const float*)pbias, nullptr, 0, 1.0f, (float*)pstat);

    // 3. finalize BN; BN+ReLU+transpose q/k
    bn_finalize<<<2, 256>>>(gq, betaq, gk, betak);
    convert_qk<<<dim3(NPIX / 32, (2 * CK) / 32, BATCH), 256>>>();

    // 4-6. fused attention
    flash_attn<<<dim3(NPIX / 128, BATCH), 256, FL_SMEM>>>(
        (const __half*)pkt2, (const __half*)pqt2, (const __half*)pZh, (__half*)pctx2);

    // 7. out conv + residual
    gemm_fp16<<<dim3(NPIX / 256, CIN / 128, BATCH), 512, GEMM_SMEM>>>(
        (const __half*)pwW2, (const __half*)pctx2, out, nullptr,
        KP_CTX, KP_CTX / 32, NPIX,
        0, (size_t)NPIX * KP_CTX, (size_t)CIN * NPIX,
        bW, x, (size_t)CIN * NPIX, 1.0f, nullptr);
}

// round 15
// speedup vs baseline: 1.0591x; 1.0392x over previous
#include <cuda_runtime.h>
#include <cuda_fp16.h>
#include <cstdint>
#include <math.h>

#define BATCH 4
#define CIN   512
#define CK    256
#define CV    256
#define QKV   768
#define NPIX  4096
#define EPSBN 1e-5f

#define KP_X   512
#define KP_QK  256
#define KP_CTX 256

// ---------------- scratch globals --------------------------------------------
static __device__ __half g_wqkv2[(size_t)QKV * KP_X];
static __device__ __half g_wW2[(size_t)CIN * KP_CTX];
static __device__ float g_bias[QKV];
static __device__ __half g_xt2[(size_t)BATCH * NPIX * KP_X];
static __device__ __half g_Zh[(size_t)BATCH * QKV * NPIX];
static __device__ float g_stat[1024];
static __device__ float g_bnA[2 * CK], g_bnB[2 * CK];
static __device__ __half g_qt2[(size_t)BATCH * NPIX * KP_QK];
static __device__ __half g_kt2[(size_t)BATCH * NPIX * KP_QK];
static __device__ __half g_ctx2[(size_t)BATCH * NPIX * KP_CTX];

// ---------------- helpers ----------------------------------------------------
__device__ __forceinline__ uint32_t smem_u32(const void* p) {
    uint32_t a;
    asm("{ .reg .u64 t; cvta.to.shared.u64 t, %1; cvt.u32.u64 %0, t; }" : "=r"(a) : "l"(p));
    return a;
}
__device__ __forceinline__ void cp16(uint32_t dst, const void* src) {
    asm volatile("cp.async.cg.shared.global [%0], [%1], 16;" :: "r"(dst), "l"(src));
}
__device__ __forceinline__ void cp_commit() { asm volatile("cp.async.commit_group;" ::: "memory"); }
__device__ __forceinline__ void cp_wait1()  { asm volatile("cp.async.wait_group 1;" ::: "memory"); }

__device__ __forceinline__ void ldsm4(uint32_t* r, uint32_t addr) {
    asm volatile("ldmatrix.sync.aligned.m8n8.x4.shared.b16 {%0,%1,%2,%3}, [%4];"
        : "=r"(r[0]), "=r"(r[1]), "=r"(r[2]), "=r"(r[3]) : "r"(addr));
}
__device__ __forceinline__ void mma16816(float* d, const uint32_t* a, uint32_t b0, uint32_t b1) {
    asm volatile(
        "mma.sync.aligned.m16n8k16.row.col.f32.f16.f16.f32 "
        "{%0,%1,%2,%3}, {%4,%5,%6,%7}, {%8,%9}, {%0,%1,%2,%3};"
        : "+f"(d[0]), "+f"(d[1]), "+f"(d[2]), "+f"(d[3])
        : "r"(a[0]), "r"(a[1]), "r"(a[2]), "r"(a[3]), "r"(b0), "r"(b1));
}
__device__ __forceinline__ uint32_t packh2(float lo, float hi) {
    __half2 h = __floats2half2_rn(lo, hi);
    return *(uint32_t*)&h;
}
__device__ __forceinline__ uint32_t ex2h2(uint32_t t) {
    uint32_t p;
    asm("ex2.approx.f16x2 %0, %1;" : "=r"(p) : "r"(t));
    return p;
}

// ---------------- generic fp16 NT GEMM on HMMA (R10 version) ------------------
#define ROWB 80
#define OPB  10240
#define STG  20480

__global__ void __launch_bounds__(256, 2)
gemm_fp16(const __half* __restrict__ A, const __half* __restrict__ B,
          float* __restrict__ C, __half* __restrict__ Ch,
          int K, int nit, int ldc,
          size_t sA, size_t sB, size_t sC,
          const float* __restrict__ bias, const float* __restrict__ resid, size_t sR,
          float alpha, float* __restrict__ stats)
{
    __shared__ __align__(16) char smem[2 * STG];
    uint32_t sb = smem_u32(smem);
    int tid = threadIdx.x, wid = tid >> 5, lane = tid & 31;
    int bz = blockIdx.z;
    int i0 = blockIdx.y * 128;
    int j0 = blockIdx.x * 128;

    const char* ap = (const char*)(A + sA * bz);
    const char* bp = (const char*)(B + sB * bz);

    const char* asrc[2]; uint32_t adst[2];
    const char* bsrc[2]; uint32_t bdst[2];
    #pragma unroll
    for (int jj = 0; jj < 2; jj++) {
        int idx = tid + 256 * jj, row = idx >> 2, seg = idx & 3;
        asrc[jj] = ap + ((size_t)(i0 + row) * K) * 2 + seg * 16;
        adst[jj] = sb + row * ROWB + seg * 16;
        bsrc[jj] = bp + ((size_t)(j0 + row) * K) * 2 + seg * 16;
        bdst[jj] = sb + OPB + row * ROWB + seg * 16;
    }

    int g = lane >> 2, tg = lane & 3;
    int mw = wid >> 1, nw = wid & 1;
    uint32_t arow = sb + (mw * 32 + (lane & 15)) * ROWB + (lane >> 4) * 16;
    uint32_t brow = sb + OPB + (nw * 64 + (lane >> 4) * 8 + (lane & 7)) * ROWB
                  + ((lane >> 3) & 1) * 16;

    float acc[2][8][4];
    #pragma unroll
    for (int t = 0; t < 2; t++)
        #pragma unroll
        for (int j = 0; j < 8; j++)
            #pragma unroll
            for (int c = 0; c < 4; c++) acc[t][j][c] = 0.f;

    #pragma unroll
    for (int jj = 0; jj < 2; jj++) { cp16(adst[jj], asrc[jj]); cp16(bdst[jj], bsrc[jj]); }
    cp_commit();

    for (int it = 0; it < nit; it++) {
        if (it + 1 < nit) {
            size_t ko = (size_t)(it + 1) * 64;
            uint32_t so = ((it + 1) & 1) * STG;
            #pragma unroll
            for (int jj = 0; jj < 2; jj++) {
                cp16(adst[jj] + so, asrc[jj] + ko);
                cp16(bdst[jj] + so, bsrc[jj] + ko);
            }
        }
        cp_commit();
        cp_wait1();
        __syncthreads();

        uint32_t so = (it & 1) * STG;
        #pragma unroll
        for (int k16 = 0; k16 < 2; k16++) {
            uint32_t kb = k16 * 32;
            uint32_t a0[4], a1[4];
            ldsm4(a0, arow + so + kb);
            ldsm4(a1, arow + 16 * ROWB + so + kb);
            #pragma unroll
            for (int j2 = 0; j2 < 4; j2++) {
                uint32_t bq[4];
                ldsm4(bq, brow + so + j2 * (16 * ROWB) + kb);
                mma16816(acc[0][2 * j2],     a0, bq[0], bq[1]);
                mma16816(acc[0][2 * j2 + 1], a0, bq[2], bq[3]);
                mma16816(acc[1][2 * j2],     a1, bq[0], bq[1]);
                mma16816(acc[1][2 * j2 + 1], a1, bq[2], bq[3]);
            }
        }
        __syncthreads();
    }

    float* cb = C ? C + sC * bz : nullptr;
    __half* hb = Ch ? Ch + sC * bz : nullptr;
    const float* rb = resid ? resid + sR * bz : nullptr;
    #pragma unroll
    for (int t = 0; t < 2; t++) {
        int r0 = i0 + mw * 32 + t * 16 + g;
        int r1 = r0 + 8;
        float bi0 = bias ? bias[r0] : 0.f;
        float bi1 = bias ? bias[r1] : 0.f;
        float s0 = 0.f, q0 = 0.f, s1 = 0.f, q1 = 0.f;
        #pragma unroll
        for (int j = 0; j < 8; j++) {
            int c = j0 + nw * 64 + j * 8 + tg * 2;
            float v0 = acc[t][j][0] * alpha + bi0;
            float v1 = acc[t][j][1] * alpha + bi0;
            float v2 = acc[t][j][2] * alpha + bi1;
            float v3 = acc[t][j][3] * alpha + bi1;
            if (rb) {
                float2 x0 = *(const float2*)(rb + (size_t)r0 * ldc + c);
                float2 x1 = *(const float2*)(rb + (size_t)r1 * ldc + c);
                v0 += x0.x; v1 += x0.y; v2 += x1.x; v3 += x1.y;
            }
            s0 += v0 + v1; q0 += v0 * v0 + v1 * v1;
            s1 += v2 + v3; q1 += v2 * v2 + v3 * v3;
            if (hb) {
                *(__half2*)(hb + (size_t)r0 * ldc + c) = __floats2half2_rn(v0, v1);
                *(__half2*)(hb + (size_t)r1 * ldc + c) = __floats2half2_rn(v2, v3);
            } else {
                *(float2*)(cb + (size_t)r0 * ldc + c) = make_float2(v0, v1);
                *(float2*)(cb + (size_t)r1 * ldc + c) = make_float2(v2, v3);
            }
        }
        if (stats) {
            s0 += __shfl_xor_sync(0xffffffffu, s0, 1); s0 += __shfl_xor_sync(0xffffffffu, s0, 2);
            q0 += __shfl_xor_sync(0xffffffffu, q0, 1); q0 += __shfl_xor_sync(0xffffffffu, q0, 2);
            s1 += __shfl_xor_sync(0xffffffffu, s1, 1); s1 += __shfl_xor_sync(0xffffffffu, s1, 2);
            q1 += __shfl_xor_sync(0xffffffffu, q1, 1); q1 += __shfl_xor_sync(0xffffffffu, q1, 2);
            if (tg == 0 && r0 < 512) { atomicAdd(&stats[r0], s0); atomicAdd(&stats[512 + r0], q0); }
            if (tg == 0 && r1 < 512) { atomicAdd(&stats[r1], s1); atomicAdd(&stats[512 + r1], q1); }
        }
    }
}

// ---------------- flash attention: K-fragments cached in registers ------------
#define KROW 528
#define VROW 144
#define SM_Q 67584
#define QSTG 33792
#define SM_V (67584 + 2*33792)
#define VSTG 36864
#define FL_SMEM (135168 + 2*36864)
#define LOG2E 1.44269504f

__global__ void __launch_bounds__(256, 1)
flash_attn(const __half* __restrict__ Kt, const __half* __restrict__ Qt,
           const __half* __restrict__ Zh, __half* __restrict__ ctx2)
{
    extern __shared__ __align__(16) char smem[];
    uint32_t sb = smem_u32(smem);
    int tid = threadIdx.x, wid = tid >> 5, lane = tid & 31;
    int g = lane >> 2, tg = lane & 3;
    int b = blockIdx.y;
    int n0 = blockIdx.x * 128;

    const char* kp = (const char*)(Kt + ((size_t)b * NPIX + n0) * CK);
    const char* qp = (const char*)(Qt + (size_t)b * NPIX * CK);
    const char* vp = (const char*)(Zh + ((size_t)b * QKV + 2 * CK) * NPIX);

    // group 0: K tile + Q0/V0
    #pragma unroll
    for (int j = 0; j < 16; j++) {
        int idx = tid + 256 * j, row = idx >> 5, seg = idx & 31;
        cp16(sb + row * KROW + seg * 16, kp + (size_t)row * 512 + seg * 16);
    }
    #pragma unroll
    for (int j = 0; j < 8; j++) {
        int idx = tid + 256 * j;
        int qrow = idx >> 5, qseg = idx & 31;
        cp16(sb + SM_Q + qrow * KROW + qseg * 16, qp + (size_t)qrow * 512 + qseg * 16);
        int vrow = idx >> 3, vseg = idx & 7;
        cp16(sb + SM_V + vrow * VROW + vseg * 16, vp + ((size_t)vrow * NPIX) * 2 + vseg * 16);
    }
    cp_commit();
    // group 1: Q1/V1
    #pragma unroll
    for (int j = 0; j < 8; j++) {
        int idx = tid + 256 * j;
        int qrow = idx >> 5, qseg = idx & 31;
        cp16(sb + SM_Q + QSTG + qrow * KROW + qseg * 16,
             qp + (size_t)(64 + qrow) * 512 + qseg * 16);
        int vrow = idx >> 3, vseg = idx & 7;
        cp16(sb + SM_V + VSTG + vrow * VROW + vseg * 16,
             vp + ((size_t)vrow * NPIX + 64) * 2 + vseg * 16);
    }
    cp_commit();

    // wait for group 0 (K + tile 0), then cache K fragments in registers
    cp_wait1();
    __syncthreads();
    uint32_t arow = sb + (wid * 16 + (lane & 15)) * KROW + (lane >> 4) * 16;
    uint32_t kf[16][4];
    #pragma unroll
    for (int k16 = 0; k16 < 16; k16++) ldsm4(kf[k16], arow + k16 * 32);

    float o[32][4];
    #pragma unroll
    for (int j = 0; j < 32; j++)
        #pragma unroll
        for (int c = 0; c < 4; c++) o[j][c] = 0.f;
    float osum[4] = {0.f, 0.f, 0.f, 0.f};
    float m0 = -1e30f, m8 = -1e30f;

    uint32_t qoff = ((lane >> 4) * 8 + (lane & 7)) * KROW + ((lane >> 3) & 1) * 16;
    uint32_t voff = ((lane >> 4) * 8 + (lane & 7)) * VROW + ((lane >> 3) & 1) * 16;
    const uint32_t ONESH2 = 0x3C003C00u;

    for (int it = 0; it < NPIX / 64; it++) {
        if (it + 1 < NPIX / 64) {
            int st = (it + 1) & 1;
            size_t mo = (size_t)(it + 1) * 64;
            #pragma unroll
            for (int j = 0; j < 8; j++) {
                int idx = tid + 256 * j;
                int qrow = idx >> 5, qseg = idx & 31;
                cp16(sb + SM_Q + st * QSTG + qrow * KROW + qseg * 16,
                     qp + ((size_t)(mo + qrow)) * 512 + qseg * 16);
                int vrow = idx >> 3, vseg = idx & 7;
                cp16(sb + SM_V + st * VSTG + vrow * VROW + vseg * 16,
                     vp + ((size_t)vrow * NPIX + mo) * 2 + vseg * 16);
            }
        }
        cp_commit();
        cp_wait1();
        __syncthreads();

        int st = it & 1;
        uint32_t qb = sb + SM_Q + st * QSTG + qoff;
        uint32_t vb = sb + SM_V + st * VSTG + voff;

        // ---- gemm1: S[16n x 64m], K'=256, A from registers ----
        float s[8][4];
        #pragma unroll
        for (int j = 0; j < 8; j++)
            #pragma unroll
            for (int c = 0; c < 4; c++) s[j][c] = 0.f;
        #pragma unroll
        for (int k16 = 0; k16 < 16; k16++) {
            #pragma unroll
            for (int j2 = 0; j2 < 4; j2++) {
                uint32_t bq[4];
                ldsm4(bq, qb + j2 * (16 * KROW) + k16 * 32);
                mma16816(s[2 * j2],     kf[k16], bq[0], bq[1]);
                mma16816(s[2 * j2 + 1], kf[k16], bq[2], bq[3]);
            }
        }
        #pragma unroll
        for (int j = 0; j < 8; j++)
            #pragma unroll
            for (int c = 0; c < 4; c++) s[j][c] *= 0.0625f;

        // ---- online softmax ----
        float mx0 = -1e30f, mx8 = -1e30f;
        #pragma unroll
        for (int j = 0; j < 8; j++) {
            mx0 = fmaxf(mx0, fmaxf(s[j][0], s[j][1]));
            mx8 = fmaxf(mx8, fmaxf(s[j][2], s[j][3]));
        }
        mx0 = fmaxf(mx0, __shfl_xor_sync(0xffffffffu, mx0, 1));
        mx0 = fmaxf(mx0, __shfl_xor_sync(0xffffffffu, mx0, 2));
        mx8 = fmaxf(mx8, __shfl_xor_sync(0xffffffffu, mx8, 1));
        mx8 = fmaxf(mx8, __shfl_xor_sync(0xffffffffu, mx8, 2));
        float nm0 = fmaxf(m0, mx0), nm8 = fmaxf(m8, mx8);
        float sc0 = __expf(m0 - nm0), sc8 = __expf(m8 - nm8);
        m0 = nm0; m8 = nm8;
        float c0 = m0 * LOG2E, c8 = m8 * LOG2E;

        uint32_t pa[8][2];
        #pragma unroll
        for (int j = 0; j < 8; j++) {
            float t0 = fmaf(s[j][0], LOG2E, -c0);
            float t1 = fmaf(s[j][1], LOG2E, -c0);
            float t2 = fmaf(s[j][2], LOG2E, -c8);
            float t3 = fmaf(s[j][3], LOG2E, -c8);
            pa[j][0] = ex2h2(packh2(t0, t1));
            pa[j][1] = ex2h2(packh2(t2, t3));
        }

        if (sc0 != 1.f || sc8 != 1.f) {
            #pragma unroll
            for (int j = 0; j < 32; j++) {
                o[j][0] *= sc0; o[j][1] *= sc0;
                o[j][2] *= sc8; o[j][3] *= sc8;
            }
            osum[0] *= sc0; osum[1] *= sc0;
            osum[2] *= sc8; osum[3] *= sc8;
        }

        // ---- gemm2: O += P . V^T ----
        #pragma unroll
        for (int t = 0; t < 4; t++) {
            uint32_t a2[4] = { pa[2 * t][0], pa[2 * t][1], pa[2 * t + 1][0], pa[2 * t + 1][1] };
            mma16816(osum, a2, ONESH2, ONESH2);
            #pragma unroll
            for (int j4 = 0; j4 < 16; j4++) {
                uint32_t bv[4];
                ldsm4(bv, vb + j4 * (16 * VROW) + t * 32);
                mma16816(o[2 * j4],     a2, bv[0], bv[1]);
                mma16816(o[2 * j4 + 1], a2, bv[2], bv[3]);
            }
        }
        __syncthreads();
    }

    float i0 = 1.f / osum[0], i8 = 1.f / osum[2];
    int nrow = n0 + wid * 16 + g;
    __half2* out0 = (__half2*)(ctx2 + ((size_t)b * NPIX + nrow) * CV);
    __half2* out8 = (__half2*)(ctx2 + ((size_t)b * NPIX + nrow + 8) * CV);
    #pragma unroll
    for (int j2 = 0; j2 < 32; j2++) {
        int cp_ = 4 * j2 + tg;
        out0[cp_] = __floats2half2_rn(o[j2][0] * i0, o[j2][1] * i0);
        out8[cp_] = __floats2half2_rn(o[j2][2] * i8, o[j2][3] * i8);
    }
}

// ---------------- prep / converts ---------------------------------------------
__global__ void __launch_bounds__(256) zero_stats()
{
    g_stat[blockIdx.x * 256 + threadIdx.x] = 0.f;
}

__global__ void __launch_bounds__(256) prep_w(
    const float* __restrict__ wq, const float* __restrict__ bq,
    const float* __restrict__ wk, const float* __restrict__ bk,
    const float* __restrict__ wv, const float* __restrict__ bv,
    const float* __restrict__ wW)
{
    int idx = blockIdx.x * 256 + threadIdx.x;
    {
        int o = idx / CIN, c = idx % CIN;
        float v = (o < CK) ? wq[o * CIN + c] : (o < 2 * CK) ? wk[(o - CK) * CIN + c]
                                                            : wv[(o - 2 * CK) * CIN + c];
        g_wqkv2[(size_t)o * KP_X + c] = __float2half(v);
    }
    if (idx < CIN * CV) {
        int co = idx / CV, cv = idx % CV;
        g_wW2[(size_t)co * KP_CTX + cv] = __float2half(wW[co * CV + cv]);
    }
    if (idx < QKV)
        g_bias[idx] = (idx < CK) ? bq[idx] : (idx < 2 * CK) ? bk[idx - CK] : bv[idx - 2 * CK];
}

__global__ void __launch_bounds__(256) transpose_x(const float* __restrict__ x)
{
    __shared__ float tile[32][33];
    int b = blockIdx.z, c0 = blockIdx.y * 32, n0 = blockIdx.x * 32;
    int tx = threadIdx.x & 31, ty = threadIdx.x >> 5;
    const float* xp = x + ((size_t)b * CIN + c0) * NPIX + n0;
    #pragma unroll
    for (int r = ty; r < 32; r += 8) tile[r][tx] = xp[(size_t)r * NPIX + tx];
    __syncthreads();
    __half* op = g_xt2 + ((size_t)b * NPIX + n0) * KP_X + c0;
    #pragma unroll
    for (int r = ty; r < 32; r += 8)
        op[(size_t)r * KP_X + tx] = __float2half(tile[tx][r]);
}

__global__ void __launch_bounds__(256) bn_finalize(
    const float* __restrict__ gq, const float* __restrict__ betaq,
    const float* __restrict__ gk, const float* __restrict__ betak)
{
    int o = blockIdx.x * 256 + threadIdx.x;
    float cnt = (float)(BATCH * NPIX);
    float mean = g_stat[o] / cnt;
    float var = g_stat[512 + o] / cnt - mean * mean;
    float inv = rsqrtf(var + EPSBN);
    float gamma = (o < CK) ? gq[o] : gk[o - CK];
    float beta  = (o < CK) ? betaq[o] : betak[o - CK];
    g_bnA[o] = gamma * inv;
    g_bnB[o] = beta - mean * gamma * inv;
}

__global__ void __launch_bounds__(256) convert_qk()
{
    __shared__ float tile[32][33];
    int b = blockIdx.z, o0 = blockIdx.y * 32, n0 = blockIdx.x * 32;
    int tx = threadIdx.x & 31, ty = threadIdx.x >> 5;
    #pragma unroll
    for (int r = ty; r < 32; r += 8) {
        int o = o0 + r;
        float z = __half2float(g_Zh[((size_t)b * QKV + o) * NPIX + n0 + tx]) * g_bnA[o] + g_bnB[o];
        tile[r][tx] = z > 0.f ? z : 0.f;
    }
    __syncthreads();
    bool isq = (o0 < CK);
    __half* base = isq ? g_qt2 : g_kt2;
    int oc = o0 & (CK - 1);
    __half* op = base + ((size_t)b * NPIX + n0) * KP_QK + oc;
    #pragma unroll
    for (int r = ty; r < 32; r += 8)
        op[(size_t)r * KP_QK + tx] = __float2half(tile[tx][r]);
}

// ---------------- launch ------------------------------------------------------
extern "C" void kernel_launch(void* const* d_in, const int* in_sizes, int n_in,
                              void* d_out, int out_size)
{
    const float* x     = (const float*)d_in[0];
    const float* wq    = (const float*)d_in[1];
    const float* bq    = (const float*)d_in[2];
    const float* gq    = (const float*)d_in[3];
    const float* betaq = (const float*)d_in[4];
    const float* wk    = (const float*)d_in[5];
    const float* bk    = (const float*)d_in[6];
    const float* gk    = (const float*)d_in[7];
    const float* betak = (const float*)d_in[8];
    const float* wv    = (const float*)d_in[9];
    const float* bv    = (const float*)d_in[10];
    const float* wW    = (const float*)d_in[11];
    const float* bW    = (const float*)d_in[12];
    float* out = (float*)d_out;

    cudaFuncSetAttribute(flash_attn, cudaFuncAttributeMaxDynamicSharedMemorySize, FL_SMEM);

    void *pwqkv2, *pwW2, *pbias, *pxt2, *pZh, *pqt2, *pkt2, *pctx2, *pstat;
    cudaGetSymbolAddress(&pwqkv2, g_wqkv2);
    cudaGetSymbolAddress(&pwW2, g_wW2);
    cudaGetSymbolAddress(&pbias, g_bias);
    cudaGetSymbolAddress(&pxt2, g_xt2);
    cudaGetSymbolAddress(&pZh, g_Zh);
    cudaGetSymbolAddress(&pqt2, g_qt2);
    cudaGetSymbolAddress(&pkt2, g_kt2);
    cudaGetSymbolAddress(&pctx2, g_ctx2);
    cudaGetSymbolAddress(&pstat, g_stat);

    // 1. prep weights/bias; transpose x; zero stats
    prep_w<<<(QKV * CIN) / 256, 256>>>(wq, bq, wk, bk, wv, bv, wW);
    transpose_x<<<dim3(NPIX / 32, CIN / 32, BATCH), 256>>>(x);
    zero_stats<<<4, 256>>>();

    // 2. qkv projection -> fp16 Zh + fused BN stats
    gemm_fp16<<<dim3(NPIX / 128, QKV / 128, BATCH), 256>>>(
        (const __half*)pwqkv2, (const __half*)pxt2, nullptr, (__half*)pZh,
        KP_X, KP_X / 32, NPIX,
        0, (size_t)NPIX * KP_X, (size_t)QKV * NPIX,
        (const float*)pbias, nullptr, 0, 1.0f, (float*)pstat);

    // 3. finalize BN; BN+ReLU+transpose q/k
    bn_finalize<<<2, 256>>>(gq, betaq, gk, betak);
    convert_qk<<<dim3(NPIX / 32, (2 * CK) / 32, BATCH), 256>>>();

    // 4-6. fused attention (K-frags in registers)
    flash_attn<<<dim3(NPIX / 128, BATCH), 256, FL_SMEM>>>(
        (const __half*)pkt2, (const __half*)pqt2, (const __half*)pZh, (__half*)pctx2);

    // 7. out conv + residual
    gemm_fp16<<<dim3(NPIX / 128, CIN / 128, BATCH), 256>>>(
        (const __half*)pwW2, (const __half*)pctx2, out, nullptr,
        KP_CTX, KP_CTX / 32, NPIX,
        0, (size_t)NPIX * KP_CTX, (size_t)CIN * NPIX,
        bW, x, (size_t)CIN * NPIX, 1.0f, nullptr);
}